// round 3
// baseline (speedup 1.0000x reference)
#include <cuda_runtime.h>
#include <cuda_bf16.h>
#include <math.h>

#define INF_F 1e10f
#define L2E   1.4426950408889634f
#define LN2   0.6931471805599453f

// ---------------- scratch (device globals) -------------------------------------
__device__ float g_norm[3u * 8192u * 64u];                 // normalized rows
__device__ float g_cost[32ull * 1024ull * 1024ull];        // row-major cost * L2E
__device__ float g_hrow[32][32][1024];                     // bottom row of tile-row ti
__device__ float g_hcol[32][32][1024];                     // right col of tile-col tj
__device__ int   g_flag[32][32][32];                       // [prob][ti][tj] done flags
__device__ int   g_counter;                                // tile dispenser
__device__ float g_R[32];                                  // DTW results (log2e-scaled)

// fast MUFU helpers (deterministic approx units; same class as __expf/__logf)
__device__ __forceinline__ float fexp2(float x) {
    float y; asm("ex2.approx.f32 %0, %1;" : "=f"(y) : "f"(x)); return y;
}
__device__ __forceinline__ float flog2(float x) {
    float y; asm("lg2.approx.f32 %0, %1;" : "=f"(y) : "f"(x)); return y;
}
typedef unsigned long long u64;
__device__ __forceinline__ u64 ffma2(u64 a, u64 b, u64 c) {
    u64 d; asm("fma.rn.f32x2 %0, %1, %2, %3;" : "=l"(d) : "l"(a), "l"(b), "l"(c)); return d;
}
__device__ __forceinline__ u64 pack2(float x) {
    u64 d; asm("mov.b64 %0, {%1, %1};" : "=l"(d) : "f"(x)); return d;
}

// ---------------- kernel 0: reset flags + counter -------------------------------
__global__ void init_kernel() {
    int t = blockIdx.x * blockDim.x + threadIdx.x;
    if (t < 32 * 32 * 32) ((int*)g_flag)[t] = 0;
    if (t == 0) g_counter = 0;
}

// ---------------- kernel 1: row-wise L2 normalize -------------------------------
__global__ void norm_kernel(const float* __restrict__ A,
                            const float* __restrict__ B,
                            const float* __restrict__ C) {
    const int sel  = blockIdx.y;
    const int lane = threadIdx.x & 31;
    const int row  = blockIdx.x * 8 + (threadIdx.x >> 5);
    const float* src = (sel == 0) ? A : ((sel == 1) ? B : C);

    float2 v = *(const float2*)(src + (size_t)row * 64 + lane * 2);
    float ss = v.x * v.x + v.y * v.y;
    #pragma unroll
    for (int o = 16; o > 0; o >>= 1) ss += __shfl_xor_sync(0xffffffffu, ss, o);
    float scale = 1.0f / fmaxf(sqrtf(ss), 1e-8f);
    float* dst = g_norm + (size_t)sel * (8192u * 64u) + (size_t)row * 64 + lane * 2;
    *(float2*)dst = make_float2(v.x * scale, v.y * scale);
}

// ---------------- kernel 2: cost = L2E*(1 - dot), row-major ----------------------
// grid (16,16,32), 64 threads, 8x8 microtile, packed f32x2 FMA
__global__ void __launch_bounds__(64) cost_kernel() {
    const int pb   = blockIdx.z;
    const int p    = pb >> 3;
    const int bat  = pb & 7;
    const int asel = p >> 1;                 // TGT(0)/OTH(1)
    const int bsel = (p & 1) ? asel : 2;     // self or X(2)

    const float* Abase = g_norm + ((size_t)asel * 8192u + (size_t)bat * 1024u) * 64u;
    const float* Bbase = g_norm + ((size_t)bsel * 8192u + (size_t)bat * 1024u) * 64u;
    const int i0 = blockIdx.x * 64;
    const int j0 = blockIdx.y * 64;

    __shared__ float sAT[64 * 64];   // sAT[k*64 + i]
    __shared__ float sBT[64 * 64];   // sBT[k*64 + j]
    const int tid = threadIdx.x;

    {
        const float4* ap = (const float4*)(Abase + (size_t)(i0 + tid) * 64);
        const float4* bp = (const float4*)(Bbase + (size_t)(j0 + tid) * 64);
        #pragma unroll
        for (int q = 0; q < 16; q++) {
            float4 va = ap[q];
            sAT[(4 * q + 0) * 64 + tid] = va.x;
            sAT[(4 * q + 1) * 64 + tid] = va.y;
            sAT[(4 * q + 2) * 64 + tid] = va.z;
            sAT[(4 * q + 3) * 64 + tid] = va.w;
            float4 vb = bp[q];
            sBT[(4 * q + 0) * 64 + tid] = vb.x;
            sBT[(4 * q + 1) * 64 + tid] = vb.y;
            sBT[(4 * q + 2) * 64 + tid] = vb.z;
            sBT[(4 * q + 3) * 64 + tid] = vb.w;
        }
    }
    __syncthreads();

    const int ti = tid >> 3;
    const int tj = tid & 7;

    u64 acc[8][4];
    #pragma unroll
    for (int r = 0; r < 8; r++)
        #pragma unroll
        for (int c = 0; c < 4; c++) acc[r][c] = 0ull;

    #pragma unroll
    for (int k = 0; k < 64; k++) {
        float4 t0 = *(const float4*)&sAT[k * 64 + ti * 8];
        float4 t1 = *(const float4*)&sAT[k * 64 + ti * 8 + 4];
        u64 a2[8];
        a2[0] = pack2(t0.x); a2[1] = pack2(t0.y); a2[2] = pack2(t0.z); a2[3] = pack2(t0.w);
        a2[4] = pack2(t1.x); a2[5] = pack2(t1.y); a2[6] = pack2(t1.z); a2[7] = pack2(t1.w);
        ulonglong2 u0 = *(const ulonglong2*)&sBT[k * 64 + tj * 8];
        ulonglong2 u1 = *(const ulonglong2*)&sBT[k * 64 + tj * 8 + 4];
        u64 b2[4] = {u0.x, u0.y, u1.x, u1.y};
        #pragma unroll
        for (int r = 0; r < 8; r++)
            #pragma unroll
            for (int c = 0; c < 4; c++)
                acc[r][c] = ffma2(a2[r], b2[c], acc[r][c]);
    }

    float* out = g_cost + ((size_t)pb << 20);
    #pragma unroll
    for (int r = 0; r < 8; r++) {
        float v[8];
        #pragma unroll
        for (int c = 0; c < 4; c++) {
            float lo, hi;
            asm("mov.b64 {%0, %1}, %2;" : "=f"(lo), "=f"(hi) : "l"(acc[r][c]));
            v[2 * c]     = fmaf(lo, -L2E, L2E);
            v[2 * c + 1] = fmaf(hi, -L2E, L2E);
        }
        float* o = out + (size_t)(i0 + ti * 8 + r) * 1024u + (j0 + tj * 8);
        *(float4*)o       = make_float4(v[0], v[1], v[2], v[3]);
        *(float4*)(o + 4) = make_float4(v[4], v[5], v[6], v[7]);
    }
}

// ---------------- kernel 3: soft-DTW, warp-per-tile wavefront pipeline -----------
// tile = 32 rows x 32 cols, 1 warp, no block sync; halos via global, flags via L2
__global__ void __launch_bounds__(512) dp_kernel() {
    const int lane  = threadIdx.x & 31;
    const int wslot = threadIdx.x >> 5;
    __shared__ float stop_s[16][36];   // [0]=corner, [1..32]=top row

    for (;;) {
        // ---- grab next tile (wave-major order) ----
        int t = 0;
        if (lane == 0) t = atomicAdd(&g_counter, 1);
        t = __shfl_sync(0xffffffffu, t, 0);
        if (t >= 32768) return;

        int w = 0, base = 0;
        for (;;) {
            int c = min(min(w + 1, 63 - w), 32) << 5;
            if (t < base + c) break;
            base += c; w++;
        }
        int r    = t - base;
        int prob = r & 31;
        int idx  = r >> 5;
        int ti   = min(31, w) - idx;
        int tj   = w - ti;

        // ---- wait for deps ----
        if (ti > 0 && lane == 0) {
            volatile int* f = &g_flag[prob][ti - 1][tj];
            while (*f == 0) __nanosleep(64);
        }
        if (tj > 0 && lane == 1) {
            volatile int* f = &g_flag[prob][ti][tj - 1];
            while (*f == 0) __nanosleep(64);
        }
        __syncwarp();
        __threadfence();

        // ---- load halos ----
        // top: stop_s[c] = R[ti*32-1][tj*32-1+c], c = 0..32
        {
            float tv;
            int gc = tj * 32 - 1 + lane;
            if (ti == 0)      tv = (tj == 0 && lane == 0) ? 0.0f : INF_F;
            else if (gc < 0)  tv = INF_F;
            else              tv = g_hrow[prob][ti - 1][gc];
            stop_s[wslot][lane] = tv;
            if (lane == 0) {
                float tv2 = (ti == 0) ? INF_F : g_hrow[prob][ti - 1][tj * 32 + 31];
                stop_s[wslot][32] = tv2;
            }
        }
        float lv = (tj == 0) ? INF_F : g_hcol[prob][tj - 1][ti * 32 + lane];

        // ---- preload cost tile row into local array ----
        float Drow[32];
        {
            const float* Dg = g_cost + ((size_t)prob << 20)
                            + (size_t)(ti * 32 + lane) * 1024u + tj * 32;
            #pragma unroll
            for (int q = 0; q < 8; q++) ((float4*)Drow)[q] = ((const float4*)Dg)[q];
        }
        __syncwarp();

        // ---- skewed recurrence: iteration s computes cell (lane, s-lane) ----
        float r_cur  = lv;       // R[lane][j-1] rolling
        float r_prev = INF_F;    // R[lane][j-2] rolling
        float up = INF_F, diag = INF_F;
        float corner = stop_s[wslot][0];

        float* hr = &g_hrow[prob][ti][tj * 32];
        float* hc = &g_hcol[prob][tj][ti * 32];

        for (int s = 0; s < 63; s++) {
            int di = s - lane;
            int dic = di < 0 ? 0 : (di > 31 ? 31 : di);
            float Dv = Drow[dic];                       // LDL, off critical path

            float u = up, dg = diag;
            float topv = stop_s[wslot][min(s + 1, 32)]; // broadcast LDS
            if (lane == 0) { u = topv; dg = corner; corner = topv; }

            float mn = fminf(fminf(u, dg), r_cur);
            float e0 = fexp2(mn - u);
            float e1 = fexp2(mn - dg);
            float e2 = fexp2(mn - r_cur);
            float curv = Dv + mn - flog2(e0 + e1 + e2);

            bool active = ((unsigned)di < 32u);
            float ncur  = active ? curv  : r_cur;
            float nprev = active ? r_cur : r_prev;

            if (active && lane == 31) hr[di] = ncur;    // bottom row out
            if (di == 31)             hc[lane] = ncur;  // right col out

            r_prev = nprev; r_cur = ncur;
            up   = __shfl_up_sync(0xffffffffu, r_cur, 1);
            diag = __shfl_up_sync(0xffffffffu, r_prev, 1);
        }

        if (ti == 31 && tj == 31 && lane == 31) g_R[prob] = r_cur;

        __threadfence();
        if (lane == 0) *(volatile int*)&g_flag[prob][ti][tj] = 1;
    }
}

// ---------------- kernel 4: combine into MSE loss --------------------------------
__global__ void combine_kernel(const float* __restrict__ labels, float* __restrict__ out) {
    const int b = threadIdx.x;
    float v = 0.0f;
    if (b < 8) {
        float sTX = g_R[0 * 8 + b];
        float sTT = g_R[1 * 8 + b];
        float sOX = g_R[2 * 8 + b];
        float sOO = g_R[3 * 8 + b];
        float diff = ((sTX - sOX) - 0.5f * (sTT - sOO)) * LN2 - labels[0];
        v = diff * diff;
    }
    #pragma unroll
    for (int o = 4; o > 0; o >>= 1) v += __shfl_down_sync(0xffffffffu, v, o);
    if (b == 0) out[0] = v * 0.125f;
}

// ---------------- launcher -------------------------------------------------------
extern "C" void kernel_launch(void* const* d_in, const int* in_sizes, int n_in,
                              void* d_out, int out_size) {
    const float* TGT    = (const float*)d_in[0];
    const float* OTH    = (const float*)d_in[1];
    const float* X      = (const float*)d_in[2];
    const float* labels = (const float*)d_in[3];
    float* out = (float*)d_out;

    init_kernel<<<64, 512>>>();
    norm_kernel<<<dim3(1024, 3), 256>>>(TGT, OTH, X);
    cost_kernel<<<dim3(16, 16, 32), 64>>>();
    dp_kernel<<<296, 512>>>();
    combine_kernel<<<1, 32>>>(labels, out);
}

// round 4
// speedup vs baseline: 3.6114x; 3.6114x over previous
#include <cuda_runtime.h>
#include <cuda_bf16.h>
#include <math.h>

#define INF_F 1e10f
#define L2E   1.4426950408889634f
#define LN2   0.6931471805599453f

// ---------------- scratch (device globals) -------------------------------------
__device__ float g_norm[3u * 8192u * 64u];            // normalized rows
__device__ float g_cost[32ull * 1024ull * 1024ull];   // row-major cost * L2E
__device__ float g_hrow[32][32][1024];                // bottom row of strip ti
__device__ int   g_prog[32][32];                      // [prob][ti] tiles completed
__device__ float g_R[32];                             // DTW results (log2-scaled)

__device__ __forceinline__ float fexp2(float x) {
    float y; asm("ex2.approx.f32 %0, %1;" : "=f"(y) : "f"(x)); return y;
}
__device__ __forceinline__ float flog2(float x) {
    float y; asm("lg2.approx.f32 %0, %1;" : "=f"(y) : "f"(x)); return y;
}
typedef unsigned long long u64;
__device__ __forceinline__ u64 ffma2(u64 a, u64 b, u64 c) {
    u64 d; asm("fma.rn.f32x2 %0, %1, %2, %3;" : "=l"(d) : "l"(a), "l"(b), "l"(c)); return d;
}
__device__ __forceinline__ u64 pack2(float x) {
    u64 d; asm("mov.b64 %0, {%1, %1};" : "=l"(d) : "f"(x)); return d;
}

// ---------------- kernel 0: reset progress counters ------------------------------
__global__ void init_kernel() {
    int t = threadIdx.x;
    if (t < 1024) ((int*)g_prog)[t] = 0;
}

// ---------------- kernel 1: row-wise L2 normalize -------------------------------
__global__ void norm_kernel(const float* __restrict__ A,
                            const float* __restrict__ B,
                            const float* __restrict__ C) {
    const int sel  = blockIdx.y;
    const int lane = threadIdx.x & 31;
    const int row  = blockIdx.x * 8 + (threadIdx.x >> 5);
    const float* src = (sel == 0) ? A : ((sel == 1) ? B : C);

    float2 v = *(const float2*)(src + (size_t)row * 64 + lane * 2);
    float ss = v.x * v.x + v.y * v.y;
    #pragma unroll
    for (int o = 16; o > 0; o >>= 1) ss += __shfl_xor_sync(0xffffffffu, ss, o);
    float scale = 1.0f / fmaxf(sqrtf(ss), 1e-8f);
    float* dst = g_norm + (size_t)sel * (8192u * 64u) + (size_t)row * 64 + lane * 2;
    *(float2*)dst = make_float2(v.x * scale, v.y * scale);
}

// ---------------- kernel 2: cost = L2E*(1 - dot), row-major ----------------------
__global__ void __launch_bounds__(64) cost_kernel() {
    const int pb   = blockIdx.z;
    const int p    = pb >> 3;
    const int bat  = pb & 7;
    const int asel = p >> 1;                 // TGT(0)/OTH(1)
    const int bsel = (p & 1) ? asel : 2;     // self or X(2)

    const float* Abase = g_norm + ((size_t)asel * 8192u + (size_t)bat * 1024u) * 64u;
    const float* Bbase = g_norm + ((size_t)bsel * 8192u + (size_t)bat * 1024u) * 64u;
    const int i0 = blockIdx.x * 64;
    const int j0 = blockIdx.y * 64;

    __shared__ float sAT[64 * 64];
    __shared__ float sBT[64 * 64];
    const int tid = threadIdx.x;

    {
        const float4* ap = (const float4*)(Abase + (size_t)(i0 + tid) * 64);
        const float4* bp = (const float4*)(Bbase + (size_t)(j0 + tid) * 64);
        #pragma unroll
        for (int q = 0; q < 16; q++) {
            float4 va = ap[q];
            sAT[(4 * q + 0) * 64 + tid] = va.x;
            sAT[(4 * q + 1) * 64 + tid] = va.y;
            sAT[(4 * q + 2) * 64 + tid] = va.z;
            sAT[(4 * q + 3) * 64 + tid] = va.w;
            float4 vb = bp[q];
            sBT[(4 * q + 0) * 64 + tid] = vb.x;
            sBT[(4 * q + 1) * 64 + tid] = vb.y;
            sBT[(4 * q + 2) * 64 + tid] = vb.z;
            sBT[(4 * q + 3) * 64 + tid] = vb.w;
        }
    }
    __syncthreads();

    const int ti = tid >> 3;
    const int tj = tid & 7;

    u64 acc[8][4];
    #pragma unroll
    for (int r = 0; r < 8; r++)
        #pragma unroll
        for (int c = 0; c < 4; c++) acc[r][c] = 0ull;

    #pragma unroll
    for (int k = 0; k < 64; k++) {
        float4 t0 = *(const float4*)&sAT[k * 64 + ti * 8];
        float4 t1 = *(const float4*)&sAT[k * 64 + ti * 8 + 4];
        u64 a2[8];
        a2[0] = pack2(t0.x); a2[1] = pack2(t0.y); a2[2] = pack2(t0.z); a2[3] = pack2(t0.w);
        a2[4] = pack2(t1.x); a2[5] = pack2(t1.y); a2[6] = pack2(t1.z); a2[7] = pack2(t1.w);
        ulonglong2 u0 = *(const ulonglong2*)&sBT[k * 64 + tj * 8];
        ulonglong2 u1 = *(const ulonglong2*)&sBT[k * 64 + tj * 8 + 4];
        u64 b2[4] = {u0.x, u0.y, u1.x, u1.y};
        #pragma unroll
        for (int r = 0; r < 8; r++)
            #pragma unroll
            for (int c = 0; c < 4; c++)
                acc[r][c] = ffma2(a2[r], b2[c], acc[r][c]);
    }

    float* out = g_cost + ((size_t)pb << 20);
    #pragma unroll
    for (int r = 0; r < 8; r++) {
        float v[8];
        #pragma unroll
        for (int c = 0; c < 4; c++) {
            float lo, hi;
            asm("mov.b64 {%0, %1}, %2;" : "=f"(lo), "=f"(hi) : "l"(acc[r][c]));
            v[2 * c]     = fmaf(lo, -L2E, L2E);
            v[2 * c + 1] = fmaf(hi, -L2E, L2E);
        }
        float* o = out + (size_t)(i0 + ti * 8 + r) * 1024u + (j0 + tj * 8);
        *(float4*)o       = make_float4(v[0], v[1], v[2], v[3]);
        *(float4*)(o + 4) = make_float4(v[4], v[5], v[6], v[7]);
    }
}

// ---------------- kernel 3: soft-DTW, static strip pipeline ----------------------
// warp (prob, ti) sweeps tiles (ti, tj=0..31); left halo carried in registers;
// top halo via g_hrow + release/acquire progress counters. No fences, no atomics.
__global__ void __launch_bounds__(128) dp_kernel() {
    const int wslot = threadIdx.x >> 5;
    const int wid   = blockIdx.x * 4 + wslot;     // 0..1023
    const int lane  = threadIdx.x & 31;
    const int prob  = wid >> 5;
    const int ti    = wid & 31;

    __shared__ float stop_s[4][36];               // per-warp top halo (33 used)

    const float* Dbase = g_cost + ((size_t)prob << 20)
                       + (size_t)(ti * 32 + lane) * 1024u;
    float*       hr_out    = &g_hrow[prob][ti][0];
    const float* hprev     = &g_hrow[prob][(ti > 0) ? (ti - 1) : 0][0];
    int*         prog_prev = &g_prog[prob][(ti > 0) ? (ti - 1) : 0];
    int*         prog_self = &g_prog[prob][ti];

    float r_cur = INF_F, r_prev = INF_F;          // carried across tiles

    for (int tj = 0; tj < 32; tj++) {
        // prefetch this tile's cost rows (independent of halo)
        float Drow[32];
        #pragma unroll
        for (int q = 0; q < 8; q++)
            ((float4*)Drow)[q] = ((const float4*)(Dbase + tj * 32))[q];

        // wait for the strip above to finish tile tj (acquire)
        if (ti > 0) {
            int v;
            do {
                asm volatile("ld.acquire.gpu.global.s32 %0, [%1];"
                             : "=r"(v) : "l"(prog_prev));
                if (v > tj) break;
                __nanosleep(32);
            } while (true);
        }

        // top halo: stop_s[c] = R[ti*32-1][tj*32-1+c], c = 0..32
        {
            float tv;
            int gc = tj * 32 - 1 + lane;
            if (ti == 0)      tv = (tj == 0 && lane == 0) ? 0.0f : INF_F;
            else if (gc < 0)  tv = INF_F;
            else              tv = __ldcg(hprev + gc);
            stop_s[wslot][lane] = tv;
            if (lane == 0)
                stop_s[wslot][32] = (ti == 0) ? INF_F : __ldcg(hprev + tj * 32 + 31);
        }
        __syncwarp();

        float corner = stop_s[wslot][0];
        float up = INF_F, dgs = INF_F;
        float* hr = hr_out + tj * 32;

        #pragma unroll 9
        for (int s = 0; s < 63; s++) {
            int di  = s - lane;
            int dic = di < 0 ? 0 : (di > 31 ? 31 : di);
            float Dv   = Drow[dic];                              // LDL, off chain
            float topv = stop_s[wslot][(s + 1) > 32 ? 32 : (s + 1)];

            float u = up, dg = dgs;
            if (lane == 0) { u = topv; dg = corner; corner = topv; }

            float mn = fminf(fminf(dg, r_cur), u);               // u joins last
            float e0 = fexp2(mn - u);
            float e1 = fexp2(mn - dg);
            float e2 = fexp2(mn - r_cur);
            float curv = (Dv + mn) - flog2((e0 + e1) + e2);

            bool  active = ((unsigned)di < 32u);
            float ncur   = active ? curv : r_cur;
            if (active && lane == 31) hr[di] = ncur;             // bottom row out
            r_prev = active ? r_cur : r_prev;
            r_cur  = ncur;

            up  = __shfl_up_sync(0xffffffffu, r_cur, 1);
            dgs = __shfl_up_sync(0xffffffffu, r_prev, 1);
        }

        // publish: release-store orders lane 31's halo STGs before the counter
        if (lane == 31) {
            int nv = tj + 1;
            asm volatile("st.release.gpu.global.s32 [%0], %1;"
                         :: "l"(prog_self), "r"(nv) : "memory");
        }
    }

    if (ti == 31 && lane == 31) g_R[prob] = r_cur;   // R[1023][1023]
}

// ---------------- kernel 4: combine into MSE loss --------------------------------
__global__ void combine_kernel(const float* __restrict__ labels, float* __restrict__ out) {
    const int b = threadIdx.x;
    float v = 0.0f;
    if (b < 8) {
        float sTX = g_R[0 * 8 + b];
        float sTT = g_R[1 * 8 + b];
        float sOX = g_R[2 * 8 + b];
        float sOO = g_R[3 * 8 + b];
        float diff = ((sTX - sOX) - 0.5f * (sTT - sOO)) * LN2 - labels[0];
        v = diff * diff;
    }
    #pragma unroll
    for (int o = 4; o > 0; o >>= 1) v += __shfl_down_sync(0xffffffffu, v, o);
    if (b == 0) out[0] = v * 0.125f;
}

// ---------------- launcher -------------------------------------------------------
extern "C" void kernel_launch(void* const* d_in, const int* in_sizes, int n_in,
                              void* d_out, int out_size) {
    const float* TGT    = (const float*)d_in[0];
    const float* OTH    = (const float*)d_in[1];
    const float* X      = (const float*)d_in[2];
    const float* labels = (const float*)d_in[3];
    float* out = (float*)d_out;

    init_kernel<<<1, 1024>>>();
    norm_kernel<<<dim3(1024, 3), 256>>>(TGT, OTH, X);
    cost_kernel<<<dim3(16, 16, 32), 64>>>();
    dp_kernel<<<256, 128>>>();
    combine_kernel<<<1, 32>>>(labels, out);
}